// round 1
// baseline (speedup 1.0000x reference)
#include <cuda_runtime.h>

// Problem constants
#define NS 5
#define ND 64
#define NH 961
#define NV 1024
#define HPAD 1087      // 63 zeros | 961 taps | 63 zeros
#define HPITCH 1088

// sp = conv_net(symbols) is batch-independent: precomputed once per launch.
__device__ float g_sp[NS * NV];

__device__ __forceinline__ float silu_f(float y) {
    return y * (1.0f / (1.0f + __expf(-y)));
}

__device__ __forceinline__ float warp_sum(float v) {
#pragma unroll
    for (int o = 16; o; o >>= 1) v += __shfl_xor_sync(0xffffffffu, v, o);
    return v;
}

// Compute 4 consecutive conv outputs o0..o0+3 via a sliding-window register ring.
// hb points at hp + (1023 - o0); output k reads hb[d - k].
__device__ __forceinline__ void conv4(const float* __restrict__ hb,
                                      const float* __restrict__ xs,
                                      float a[4]) {
    float hm1 = hb[-1], hm2 = hb[-2], hm3 = hb[-3];
    float a0 = 0.f, a1 = 0.f, a2 = 0.f, a3 = 0.f;
#pragma unroll 16
    for (int d = 0; d < ND; d++) {
        float h0 = hb[d];
        float xv = xs[d];
        a0 = fmaf(xv, h0,  a0);
        a1 = fmaf(xv, hm1, a1);
        a2 = fmaf(xv, hm2, a2);
        a3 = fmaf(xv, hm3, a3);
        hm3 = hm2; hm2 = hm1; hm1 = h0;
    }
    a[0] = a0; a[1] = a1; a[2] = a2; a[3] = a3;
}

// --------------------------------------------------------------------------
// Kernel A: sp = LayerNorm(silu(conv(symbols, h))) — 5 blocks, one per s.
// --------------------------------------------------------------------------
__global__ __launch_bounds__(256) void sp_kernel(
    const float* __restrict__ h, const float* __restrict__ symbols,
    const float* __restrict__ gamma, const float* __restrict__ beta) {
    __shared__ float hp[HPAD];
    __shared__ float xs[ND];
    __shared__ float red[2];
    const int s = blockIdx.x;
    const int t = threadIdx.x;

    if (t < 2) red[t] = 0.f;
    for (int i = t; i < HPAD; i += 256) hp[i] = 0.f;
    __syncthreads();
    for (int i = t; i < NH; i += 256) hp[63 + i] = h[s * NH + i];
    if (t < ND) xs[t] = symbols[s * ND + t];
    __syncthreads();

    const int o0 = 4 * t;
    float a[4];
    conv4(hp + (1023 - o0), xs, a);

    float sm = 0.f, sq = 0.f;
#pragma unroll
    for (int k = 0; k < 4; k++) {
        a[k] = silu_f(a[k]);
        sm += a[k];
        sq += a[k] * a[k];
    }
    sm = warp_sum(sm);
    sq = warp_sum(sq);
    if ((t & 31) == 0) { atomicAdd(&red[0], sm); atomicAdd(&red[1], sq); }
    __syncthreads();

    const float mu = red[0] * (1.f / NV);
    const float var = red[1] * (1.f / NV) - mu * mu;
    const float rstd = rsqrtf(var + 1e-3f);
#pragma unroll
    for (int k = 0; k < 4; k++) {
        const int o = o0 + k;
        g_sp[s * NV + o] = (a[k] - mu) * rstd * gamma[o] + beta[o];
    }
}

// --------------------------------------------------------------------------
// Kernel B: fully fused per-batch pipeline. One CTA per batch element.
//   conv -> silu -> LN (vp stays in SMEM, never hits HBM)
//   -> sign scores -> softmax(5) -> einsum -> silu -> out
// --------------------------------------------------------------------------
__global__ __launch_bounds__(256) void main_kernel(
    const float* __restrict__ values, const float* __restrict__ h,
    const float* __restrict__ gamma, const float* __restrict__ beta,
    float* __restrict__ out) {
    __shared__ float hp[NS][HPITCH];      // zero-padded taps, per s
    __shared__ float xs[NS][ND];
    __shared__ float vp[NS][NV];          // normalized conv-net output
    __shared__ float sums[NS], sumsq[NS];
    __shared__ float spart[25][8];        // per-warp score partials
    __shared__ float prob[NS][NS];        // softmax(scores)

    const int b = blockIdx.x;
    const int t = threadIdx.x;
    const int warp = t >> 5, lane = t & 31;

    if (t < NS) { sums[t] = 0.f; sumsq[t] = 0.f; }
    for (int i = t; i < NS * HPITCH; i += 256) (&hp[0][0])[i] = 0.f;
    __syncthreads();
    for (int i = t; i < NS * NH; i += 256) {
        const int s = i / NH, j = i % NH;
        hp[s][63 + j] = h[i];
    }
    for (int i = t; i < NS * ND; i += 256)
        (&xs[0][0])[i] = values[(size_t)b * (NS * ND) + i];
    __syncthreads();

    // --- conv + silu, keep values in registers across the reduction sync ---
    const int o0 = 4 * t;
    float sil[NS][4];
#pragma unroll
    for (int s = 0; s < NS; s++) {
        float a[4];
        conv4(&hp[s][1023 - o0], xs[s], a);
        float sm = 0.f, sq = 0.f;
#pragma unroll
        for (int k = 0; k < 4; k++) {
            const float v = silu_f(a[k]);
            sil[s][k] = v;
            sm += v;
            sq += v * v;
        }
        sm = warp_sum(sm);
        sq = warp_sum(sq);
        if (lane == 0) { atomicAdd(&sums[s], sm); atomicAdd(&sumsq[s], sq); }
    }
    __syncthreads();

    // --- layernorm into SMEM ---
#pragma unroll
    for (int s = 0; s < NS; s++) {
        const float mu = sums[s] * (1.f / NV);
        const float rstd = rsqrtf(sumsq[s] * (1.f / NV) - mu * mu + 1e-3f);
#pragma unroll
        for (int k = 0; k < 4; k++) {
            const int o = o0 + k;
            vp[s][o] = (sil[s][k] - mu) * rstd * gamma[o] + beta[o];
        }
    }
    __syncthreads();

    // --- scores[j][i] = mean_v sign(vp[i][v]) * sign(vp[i][v] + sp[j][v]) ---
    float acc[25];
#pragma unroll
    for (int p = 0; p < 25; p++) acc[p] = 0.f;
    for (int v = t; v < NV; v += 256) {
        float a[NS], sgn[NS], spv[NS];
#pragma unroll
        for (int i = 0; i < NS; i++) {
            a[i] = vp[i][v];
            sgn[i] = (a[i] > 0.f) ? 1.f : -1.f;
        }
#pragma unroll
        for (int j = 0; j < NS; j++) spv[j] = g_sp[j * NV + v];
#pragma unroll
        for (int j = 0; j < NS; j++)
#pragma unroll
            for (int i = 0; i < NS; i++) {
                const float c = a[i] + spv[j];
                acc[j * NS + i] += (c > 0.f) ? sgn[i] : -sgn[i];
            }
    }
#pragma unroll
    for (int p = 0; p < 25; p++) {
        const float v = warp_sum(acc[p]);
        if (lane == 0) spart[p][warp] = v;
    }
    __syncthreads();
    if (t < 25) {
        float sm = 0.f;
#pragma unroll
        for (int w = 0; w < 8; w++) sm += spart[t][w];
        spart[t][0] = sm * (1.f / NV);
    }
    __syncthreads();
    if (t < NS) {
        float sc[NS], m = -1e30f;
#pragma unroll
        for (int i = 0; i < NS; i++) {
            sc[i] = spart[t * NS + i][0];
            m = fmaxf(m, sc[i]);
        }
        float ssum = 0.f;
#pragma unroll
        for (int i = 0; i < NS; i++) { sc[i] = __expf(sc[i] - m); ssum += sc[i]; }
        const float inv = 1.f / ssum;
#pragma unroll
        for (int i = 0; i < NS; i++) prob[t][i] = sc[i] * inv;
    }
    __syncthreads();

    // --- att = scores @ vp ; out = silu(att * sp) ; vectorized store ---
    float4* out4 = (float4*)(out + (size_t)b * (NS * NV));
#pragma unroll
    for (int j = 0; j < NS; j++) {
        const float p0 = prob[j][0], p1 = prob[j][1], p2 = prob[j][2],
                    p3 = prob[j][3], p4 = prob[j][4];
        float r[4];
#pragma unroll
        for (int k = 0; k < 4; k++) {
            const int o = o0 + k;
            const float atv = p0 * vp[0][o] + p1 * vp[1][o] + p2 * vp[2][o] +
                              p3 * vp[3][o] + p4 * vp[4][o];
            r[k] = silu_f(atv * g_sp[j * NV + o]);
        }
        float4 v4;
        v4.x = r[0]; v4.y = r[1]; v4.z = r[2]; v4.w = r[3];
        out4[(j * NV + o0) >> 2] = v4;
    }
}

extern "C" void kernel_launch(void* const* d_in, const int* in_sizes, int n_in,
                              void* d_out, int out_size) {
    const float* values  = (const float*)d_in[0];
    const float* h       = (const float*)d_in[1];
    const float* symbols = (const float*)d_in[2];
    const float* gamma   = (const float*)d_in[3];
    const float* beta    = (const float*)d_in[4];
    float* out = (float*)d_out;

    const int B = in_sizes[0] / (NS * ND);

    sp_kernel<<<NS, 256>>>(h, symbols, gamma, beta);
    main_kernel<<<B, 256>>>(values, h, gamma, beta, out);
}

// round 2
// speedup vs baseline: 1.7783x; 1.7783x over previous
#include <cuda_runtime.h>

// Problem constants
#define NS 5
#define ND 64
#define NH 961
#define NV 1024
#define HPITCH 1092   // 63 zeros | 961 taps | 68 zeros ; 4368 B/row (16B-aligned)

// Precomputed once per launch:
__device__ float g_hp[NS][HPITCH];   // zero-padded taps
__device__ float g_sp[NS][NV];       // sp = conv_net(symbols), batch-independent

__device__ __forceinline__ float silu_f(float y) {
    return y * (1.0f / (1.0f + __expf(-y)));
}

__device__ __forceinline__ float warp_sum(float v) {
#pragma unroll
    for (int o = 16; o; o >>= 1) v += __shfl_xor_sync(0xffffffffu, v, o);
    return v;
}

// a[k] = sum_{d=0..63} xs[d] * g[d + 3 - k]   (k = 0..3)
// g is 16-byte aligned; reads g[0..67]. All loads are float4:
//  - h loads: lane stride 16B -> covers all 32 banks exactly once (conflict-free)
//  - x loads: uniform broadcast
__device__ __forceinline__ void conv4q(const float* __restrict__ g,
                                       const float* __restrict__ xs,
                                       float a[4]) {
    const float4* g4 = (const float4*)g;
    const float4* x4 = (const float4*)xs;
    float4 G = g4[0];
    float a0 = 0.f, a1 = 0.f, a2 = 0.f, a3 = 0.f;
#pragma unroll 4
    for (int m = 0; m < 16; m++) {
        const float4 Gn = g4[m + 1];
        const float4 X = x4[m];
        // d = 4m+0 : window g[4m .. 4m+3]
        a3 = fmaf(X.x, G.x, a3); a2 = fmaf(X.x, G.y, a2);
        a1 = fmaf(X.x, G.z, a1); a0 = fmaf(X.x, G.w, a0);
        // d = 4m+1
        a3 = fmaf(X.y, G.y, a3); a2 = fmaf(X.y, G.z, a2);
        a1 = fmaf(X.y, G.w, a1); a0 = fmaf(X.y, Gn.x, a0);
        // d = 4m+2
        a3 = fmaf(X.z, G.z, a3); a2 = fmaf(X.z, G.w, a2);
        a1 = fmaf(X.z, Gn.x, a1); a0 = fmaf(X.z, Gn.y, a0);
        // d = 4m+3
        a3 = fmaf(X.w, G.w, a3); a2 = fmaf(X.w, Gn.x, a2);
        a1 = fmaf(X.w, Gn.y, a1); a0 = fmaf(X.w, Gn.z, a0);
        G = Gn;
    }
    a[0] = a0; a[1] = a1; a[2] = a2; a[3] = a3;
}

// --------------------------------------------------------------------------
// Kernel 0: build zero-padded h once.
// --------------------------------------------------------------------------
__global__ __launch_bounds__(256) void pad_kernel(const float* __restrict__ h) {
    const int i = blockIdx.x * 256 + threadIdx.x;
    if (i < NS * HPITCH) {
        const int s = i / HPITCH, j = i % HPITCH;
        (&g_hp[0][0])[i] = (j >= 63 && j < 63 + NH) ? h[s * NH + (j - 63)] : 0.f;
    }
}

// --------------------------------------------------------------------------
// Kernel 1: sp = LayerNorm(silu(conv(symbols))) — 5 blocks, one per s.
// --------------------------------------------------------------------------
__global__ __launch_bounds__(256) void sp_kernel(
    const float* __restrict__ symbols,
    const float* __restrict__ gamma, const float* __restrict__ beta) {
    __shared__ float hp[HPITCH];
    __shared__ float xs[ND];
    __shared__ float wsum[8], wsq[8], mu_rs[2];
    const int s = blockIdx.x;
    const int t = threadIdx.x;
    const int warp = t >> 5, lane = t & 31;

    {
        const float4* src = (const float4*)(&g_hp[s][0]);
        float4* dst = (float4*)hp;
        for (int i = t; i < HPITCH / 4; i += 256) dst[i] = src[i];
        if (t < ND) xs[t] = symbols[s * ND + t];
    }
    __syncthreads();

    const int o0 = 4 * t;
    float a[4];
    conv4q(hp + (1020 - o0), xs, a);

    float sm = 0.f, sq = 0.f;
#pragma unroll
    for (int k = 0; k < 4; k++) {
        a[k] = silu_f(a[k]);
        sm += a[k];
        sq += a[k] * a[k];
    }
    sm = warp_sum(sm);
    sq = warp_sum(sq);
    if (lane == 0) { wsum[warp] = sm; wsq[warp] = sq; }
    __syncthreads();
    if (t == 0) {
        float s1 = 0.f, s2 = 0.f;
#pragma unroll
        for (int w = 0; w < 8; w++) { s1 += wsum[w]; s2 += wsq[w]; }
        const float mu = s1 * (1.f / NV);
        mu_rs[0] = mu;
        mu_rs[1] = rsqrtf(s2 * (1.f / NV) - mu * mu + 1e-3f);
    }
    __syncthreads();
    const float mu = mu_rs[0], rstd = mu_rs[1];
#pragma unroll
    for (int k = 0; k < 4; k++) {
        const int o = o0 + k;
        g_sp[s][o] = (a[k] - mu) * rstd * gamma[o] + beta[o];
    }
}

// --------------------------------------------------------------------------
// Kernel 2: fully fused per-batch pipeline. One CTA / batch element.
// vp never leaves registers (each thread owns exactly columns 4t..4t+3).
// --------------------------------------------------------------------------
__global__ __launch_bounds__(256) void main_kernel(
    const float* __restrict__ values,
    const float* __restrict__ gamma, const float* __restrict__ beta,
    float* __restrict__ out) {
    __shared__ float hp[NS][HPITCH];      // 21840 B
    __shared__ float xs[NS][ND];          //  1280 B
    __shared__ float wsum[NS][8], wsq[NS][8];
    __shared__ float mu_s[NS], rs_s[NS];
    __shared__ float spart[25][8];
    __shared__ float prob[NS][NS];

    const int b = blockIdx.x;
    const int t = threadIdx.x;
    const int warp = t >> 5, lane = t & 31;
    const int o0 = 4 * t;

    {   // copy padded taps + this batch's x into smem (all float4)
        const float4* src = (const float4*)(&g_hp[0][0]);
        float4* dst = (float4*)(&hp[0][0]);
        for (int i = t; i < NS * HPITCH / 4; i += 256) dst[i] = src[i];
        const float4* v4 = (const float4*)(values + (size_t)b * (NS * ND));
        if (t < NS * ND / 4) ((float4*)(&xs[0][0]))[t] = v4[t];
    }
    __syncthreads();

    // ---- conv + silu ----
    float vpreg[NS][4];
#pragma unroll
    for (int s = 0; s < NS; s++) {
        float a[4];
        conv4q(&hp[s][1020 - o0], xs[s], a);
        float sm = 0.f, sq = 0.f;
#pragma unroll
        for (int k = 0; k < 4; k++) {
            const float v = silu_f(a[k]);
            vpreg[s][k] = v;
            sm += v;
            sq += v * v;
        }
        sm = warp_sum(sm);
        sq = warp_sum(sq);
        if (lane == 0) { wsum[s][warp] = sm; wsq[s][warp] = sq; }
    }
    __syncthreads();
    if (t < NS) {
        float s1 = 0.f, s2 = 0.f;
#pragma unroll
        for (int w = 0; w < 8; w++) { s1 += wsum[t][w]; s2 += wsq[t][w]; }
        const float mu = s1 * (1.f / NV);
        mu_s[t] = mu;
        rs_s[t] = rsqrtf(s2 * (1.f / NV) - mu * mu + 1e-3f);
    }
    __syncthreads();

    // ---- layernorm in registers ----
    const float4 gm4 = ((const float4*)gamma)[t];
    const float4 bt4 = ((const float4*)beta)[t];
    const float gmk[4] = {gm4.x, gm4.y, gm4.z, gm4.w};
    const float btk[4] = {bt4.x, bt4.y, bt4.z, bt4.w};
#pragma unroll
    for (int s = 0; s < NS; s++) {
        const float mu = mu_s[s], rstd = rs_s[s];
#pragma unroll
        for (int k = 0; k < 4; k++)
            vpreg[s][k] = (vpreg[s][k] - mu) * rstd * gmk[k] + btk[k];
    }

    // ---- scores[j][i] = mean_v sign(vp[i][v]) * sign(vp[i][v] + sp[j][v]) ----
    float4 SP[NS];
#pragma unroll
    for (int j = 0; j < NS; j++) SP[j] = ((const float4*)(&g_sp[j][0]))[t];

    float acc[25];
#pragma unroll
    for (int p = 0; p < 25; p++) acc[p] = 0.f;
#pragma unroll
    for (int j = 0; j < NS; j++) {
        const float spv[4] = {SP[j].x, SP[j].y, SP[j].z, SP[j].w};
#pragma unroll
        for (int i = 0; i < NS; i++) {
            float a = 0.f;
#pragma unroll
            for (int k = 0; k < 4; k++) {
                const float x = vpreg[i][k];
                const float sg = (x > 0.f) ? 1.f : -1.f;
                const float c = x + spv[k];
                a += (c > 0.f) ? sg : -sg;
            }
            acc[j * NS + i] = a;
        }
    }
#pragma unroll
    for (int p = 0; p < 25; p++) {
        const float v = warp_sum(acc[p]);
        if (lane == 0) spart[p][warp] = v;
    }
    __syncthreads();
    if (t < 25) {
        float sm = 0.f;
#pragma unroll
        for (int w = 0; w < 8; w++) sm += spart[t][w];
        spart[t][0] = sm * (1.f / NV);
    }
    __syncthreads();
    if (t < NS) {
        float sc[NS], m = -1e30f;
#pragma unroll
        for (int i = 0; i < NS; i++) {
            sc[i] = spart[t * NS + i][0];
            m = fmaxf(m, sc[i]);
        }
        float ssum = 0.f;
#pragma unroll
        for (int i = 0; i < NS; i++) { sc[i] = __expf(sc[i] - m); ssum += sc[i]; }
        const float inv = 1.f / ssum;
#pragma unroll
        for (int i = 0; i < NS; i++) prob[t][i] = sc[i] * inv;
    }
    __syncthreads();

    // ---- att = prob @ vp (all registers) ; out = silu(att * sp) ----
    float4* out4 = (float4*)(out + (size_t)b * (NS * NV));
#pragma unroll
    for (int j = 0; j < NS; j++) {
        const float p0 = prob[j][0], p1 = prob[j][1], p2 = prob[j][2],
                    p3 = prob[j][3], p4 = prob[j][4];
        const float spv[4] = {SP[j].x, SP[j].y, SP[j].z, SP[j].w};
        float r[4];
#pragma unroll
        for (int k = 0; k < 4; k++) {
            const float atv = p0 * vpreg[0][k] + p1 * vpreg[1][k] +
                              p2 * vpreg[2][k] + p3 * vpreg[3][k] +
                              p4 * vpreg[4][k];
            r[k] = silu_f(atv * spv[k]);
        }
        float4 v4;
        v4.x = r[0]; v4.y = r[1]; v4.z = r[2]; v4.w = r[3];
        out4[(j * NV + o0) >> 2] = v4;
    }
}

extern "C" void kernel_launch(void* const* d_in, const int* in_sizes, int n_in,
                              void* d_out, int out_size) {
    const float* values  = (const float*)d_in[0];
    const float* h       = (const float*)d_in[1];
    const float* symbols = (const float*)d_in[2];
    const float* gamma   = (const float*)d_in[3];
    const float* beta    = (const float*)d_in[4];
    float* out = (float*)d_out;

    const int B = in_sizes[0] / (NS * ND);

    pad_kernel<<<(NS * HPITCH + 255) / 256, 256>>>(h);
    sp_kernel<<<NS, 256>>>(symbols, gamma, beta);
    main_kernel<<<B, 256>>>(values, gamma, beta, out);
}

// round 3
// speedup vs baseline: 2.0455x; 1.1502x over previous
#include <cuda_runtime.h>

// Problem constants
#define NS 5
#define ND 64
#define NH 961
#define NV 1024
#define HPITCH 1092   // 63 zeros | 961 taps | 68 zeros ; 16B-aligned rows

// Precomputed once per launch:
__device__ float g_hp[NS][HPITCH];   // zero-padded taps
__device__ float g_sp[NS][NV];       // sp = conv_net(symbols), batch-independent

__device__ __forceinline__ float silu_f(float y) {
    return y * (1.0f / (1.0f + __expf(-y)));
}

__device__ __forceinline__ float warp_sum(float v) {
#pragma unroll
    for (int o = 16; o; o >>= 1) v += __shfl_xor_sync(0xffffffffu, v, o);
    return v;
}

// packed dual-FMA: acc(lo,hi) += x(lo,hi) * g(lo,hi), elementwise fp32
__device__ __forceinline__ void ffma2(unsigned long long& acc,
                                      unsigned long long x,
                                      unsigned long long g) {
    asm("fma.rn.f32x2 %0, %1, %2, %0;" : "+l"(acc) : "l"(x), "l"(g));
}
__device__ __forceinline__ float u64lo(unsigned long long u) {
    return __uint_as_float((unsigned)u);
}
__device__ __forceinline__ float u64hi(unsigned long long u) {
    return __uint_as_float((unsigned)(u >> 32));
}

// a[k] = sum_{d=0..63} xs[d] * g[d + 3 - k]   (k = 0..3), g 16B-aligned.
// k=3,k=1 use even-offset pairs -> fma.rn.f32x2 on natural 64-bit reg pairs.
// k=2,k=0 pairs are odd-offset -> scalar FFMA from the same register window.
// fma-pipe: 12 inst / 16 MACs (vs 16 scalar).
__device__ __forceinline__ void conv4m(const float* __restrict__ g,
                                       const float* __restrict__ xs,
                                       float a[4]) {
    const ulonglong2* g2 = (const ulonglong2*)g;   // ld.shared.v2.u64
    const ulonglong2* x2 = (const ulonglong2*)xs;
    unsigned long long A3 = 0ull, A1 = 0ull;
    float a2 = 0.f, a0 = 0.f;
    ulonglong2 G = g2[0];
#pragma unroll 4
    for (int m = 0; m < 16; m++) {
        const ulonglong2 Gn = g2[m + 1];
        const ulonglong2 X = x2[m];
        // paired outputs
        ffma2(A3, X.x, G.x);     // d=4m,4m+1   : g[4m..4m+1]
        ffma2(A1, X.x, G.y);     // d=4m,4m+1   : g[4m+2..4m+3]
        ffma2(A3, X.y, G.y);     // d=4m+2,4m+3 : g[4m+2..4m+3]
        ffma2(A1, X.y, Gn.x);    // d=4m+2,4m+3 : g[4m+4..4m+5]
        // scalar outputs (odd-offset pairs)
        const float X0 = u64lo(X.x), X1 = u64hi(X.x);
        const float X2 = u64lo(X.y), X3 = u64hi(X.y);
        const float h1 = u64hi(G.x),  h2 = u64lo(G.y),  h3 = u64hi(G.y);
        const float h4 = u64lo(Gn.x), h5 = u64hi(Gn.x), h6 = u64lo(Gn.y);
        a2 = fmaf(X0, h1, a2); a2 = fmaf(X1, h2, a2);
        a2 = fmaf(X2, h3, a2); a2 = fmaf(X3, h4, a2);
        a0 = fmaf(X0, h3, a0); a0 = fmaf(X1, h4, a0);
        a0 = fmaf(X2, h5, a0); a0 = fmaf(X3, h6, a0);
        G = Gn;
    }
    a[3] = u64lo(A3) + u64hi(A3);
    a[1] = u64lo(A1) + u64hi(A1);
    a[2] = a2;
    a[0] = a0;
}

// --------------------------------------------------------------------------
// Kernel 1: pads h into g_hp AND computes sp. 5 blocks, one per s.
// --------------------------------------------------------------------------
__global__ __launch_bounds__(256) void sp_kernel(
    const float* __restrict__ h, const float* __restrict__ symbols,
    const float* __restrict__ gamma, const float* __restrict__ beta) {
    __shared__ float hp[HPITCH];
    __shared__ float xs[ND];
    __shared__ float wsum[8], wsq[8], mu_rs[2];
    const int s = blockIdx.x;
    const int t = threadIdx.x;
    const int warp = t >> 5, lane = t & 31;

    for (int i = t; i < HPITCH; i += 256) {
        const float v = (i >= 63 && i < 63 + NH) ? h[s * NH + (i - 63)] : 0.f;
        hp[i] = v;
        g_hp[s][i] = v;
    }
    if (t < ND) xs[t] = symbols[s * ND + t];
    __syncthreads();

    const int o0 = 4 * t;
    float a[4];
    conv4m(hp + (1020 - o0), xs, a);

    float sm = 0.f, sq = 0.f;
#pragma unroll
    for (int k = 0; k < 4; k++) {
        a[k] = silu_f(a[k]);
        sm += a[k];
        sq += a[k] * a[k];
    }
    sm = warp_sum(sm);
    sq = warp_sum(sq);
    if (lane == 0) { wsum[warp] = sm; wsq[warp] = sq; }
    __syncthreads();
    if (t == 0) {
        float s1 = 0.f, s2 = 0.f;
#pragma unroll
        for (int w = 0; w < 8; w++) { s1 += wsum[w]; s2 += wsq[w]; }
        const float mu = s1 * (1.f / NV);
        mu_rs[0] = mu;
        mu_rs[1] = rsqrtf(s2 * (1.f / NV) - mu * mu + 1e-3f);
    }
    __syncthreads();
    const float mu = mu_rs[0], rstd = mu_rs[1];
#pragma unroll
    for (int k = 0; k < 4; k++) {
        const int o = o0 + k;
        g_sp[s][o] = (a[k] - mu) * rstd * gamma[o] + beta[o];
    }
}

// --------------------------------------------------------------------------
// Kernel 2: fully fused per-batch pipeline. One CTA / batch element.
// vp never leaves registers (each thread owns columns 4t..4t+3).
// --------------------------------------------------------------------------
__global__ __launch_bounds__(256) void main_kernel(
    const float* __restrict__ values,
    const float* __restrict__ gamma, const float* __restrict__ beta,
    float* __restrict__ out) {
    __shared__ float hp[NS][HPITCH];
    __shared__ float xs[NS][ND];
    __shared__ float wsum[NS][8], wsq[NS][8];
    __shared__ float mu_s[NS], rs_s[NS];
    __shared__ int   spart[25][8];
    __shared__ float prob[NS][NS];

    const int b = blockIdx.x;
    const int t = threadIdx.x;
    const int warp = t >> 5, lane = t & 31;
    const int o0 = 4 * t;

    {   // copy padded taps + this batch's x into smem (all float4)
        const float4* src = (const float4*)(&g_hp[0][0]);
        float4* dst = (float4*)(&hp[0][0]);
        for (int i = t; i < NS * HPITCH / 4; i += 256) dst[i] = src[i];
        const float4* v4 = (const float4*)(values + (size_t)b * (NS * ND));
        if (t < NS * ND / 4) ((float4*)(&xs[0][0]))[t] = v4[t];
    }
    __syncthreads();

    // ---- conv + silu ----
    float vpreg[NS][4];
#pragma unroll
    for (int s = 0; s < NS; s++) {
        float a[4];
        conv4m(&hp[s][1020 - o0], xs[s], a);
        float sm = 0.f, sq = 0.f;
#pragma unroll
        for (int k = 0; k < 4; k++) {
            const float v = silu_f(a[k]);
            vpreg[s][k] = v;
            sm += v;
            sq += v * v;
        }
        sm = warp_sum(sm);
        sq = warp_sum(sq);
        if (lane == 0) { wsum[s][warp] = sm; wsq[s][warp] = sq; }
    }
    __syncthreads();
    if (t < NS) {
        float s1 = 0.f, s2 = 0.f;
#pragma unroll
        for (int w = 0; w < 8; w++) { s1 += wsum[t][w]; s2 += wsq[t][w]; }
        const float mu = s1 * (1.f / NV);
        mu_s[t] = mu;
        rs_s[t] = rsqrtf(s2 * (1.f / NV) - mu * mu + 1e-3f);
    }
    __syncthreads();

    // ---- layernorm in registers ----
    const float4 gm4 = ((const float4*)gamma)[t];
    const float4 bt4 = ((const float4*)beta)[t];
    const float gmk[4] = {gm4.x, gm4.y, gm4.z, gm4.w};
    const float btk[4] = {bt4.x, bt4.y, bt4.z, bt4.w};
#pragma unroll
    for (int s = 0; s < NS; s++) {
        const float mu = mu_s[s], rstd = rs_s[s];
#pragma unroll
        for (int k = 0; k < 4; k++)
            vpreg[s][k] = (vpreg[s][k] - mu) * rstd * gmk[k] + btk[k];
    }

    // ---- scores[j][i] = mean_v sign(vp_i) * sign(vp_i + sp_j) ----
    // sign(x)sign(x+sp) = 1 - 2*(signbit(x) ^ signbit(x+sp)); count flips as ints.
    float4 SP[NS];
#pragma unroll
    for (int j = 0; j < NS; j++) SP[j] = ((const float4*)(&g_sp[j][0]))[t];

    unsigned uv[NS][4];
#pragma unroll
    for (int i = 0; i < NS; i++)
#pragma unroll
        for (int k = 0; k < 4; k++) uv[i][k] = __float_as_uint(vpreg[i][k]);

    int acc[25];
#pragma unroll
    for (int p = 0; p < 25; p++) acc[p] = 0;
#pragma unroll
    for (int j = 0; j < NS; j++) {
        const float spv[4] = {SP[j].x, SP[j].y, SP[j].z, SP[j].w};
#pragma unroll
        for (int i = 0; i < NS; i++) {
            int a = 0;
#pragma unroll
            for (int k = 0; k < 4; k++) {
                const float c = vpreg[i][k] + spv[k];
                a += (int)((uv[i][k] ^ __float_as_uint(c)) >> 31);
            }
            acc[j * NS + i] = a;
        }
    }
#pragma unroll
    for (int p = 0; p < 25; p++) {
        const int v = __reduce_add_sync(0xffffffffu, acc[p]);
        if (lane == 0) spart[p][warp] = v;
    }
    __syncthreads();
    if (t < 25) {
        int sm = 0;
#pragma unroll
        for (int w = 0; w < 8; w++) sm += spart[t][w];
        // score = (NV - 2*flips)/NV, reuse spart as float storage
        ((float*)&spart[t][0])[0] = (float)(NV - 2 * sm) * (1.f / NV);
    }
    __syncthreads();
    if (t < NS) {
        float sc[NS], m = -1e30f;
#pragma unroll
        for (int i = 0; i < NS; i++) {
            sc[i] = ((float*)&spart[t * NS + i][0])[0];
            m = fmaxf(m, sc[i]);
        }
        float ssum = 0.f;
#pragma unroll
        for (int i = 0; i < NS; i++) { sc[i] = __expf(sc[i] - m); ssum += sc[i]; }
        const float inv = 1.f / ssum;
#pragma unroll
        for (int i = 0; i < NS; i++) prob[t][i] = sc[i] * inv;
    }
    __syncthreads();

    // ---- att = prob @ vp (registers) ; out = silu(att * sp) ----
    float4* out4 = (float4*)(out + (size_t)b * (NS * NV));
#pragma unroll
    for (int j = 0; j < NS; j++) {
        const float p0 = prob[j][0], p1 = prob[j][1], p2 = prob[j][2],
                    p3 = prob[j][3], p4 = prob[j][4];
        const float spv[4] = {SP[j].x, SP[j].y, SP[j].z, SP[j].w};
        float r[4];
#pragma unroll
        for (int k = 0; k < 4; k++) {
            const float atv = p0 * vpreg[0][k] + p1 * vpreg[1][k] +
                              p2 * vpreg[2][k] + p3 * vpreg[3][k] +
                              p4 * vpreg[4][k];
            r[k] = silu_f(atv * spv[k]);
        }
        float4 v4;
        v4.x = r[0]; v4.y = r[1]; v4.z = r[2]; v4.w = r[3];
        out4[(j * NV + o0) >> 2] = v4;
    }
}

extern "C" void kernel_launch(void* const* d_in, const int* in_sizes, int n_in,
                              void* d_out, int out_size) {
    const float* values  = (const float*)d_in[0];
    const float* h       = (const float*)d_in[1];
    const float* symbols = (const float*)d_in[2];
    const float* gamma   = (const float*)d_in[3];
    const float* beta    = (const float*)d_in[4];
    float* out = (float*)d_out;

    const int B = in_sizes[0] / (NS * ND);

    sp_kernel<<<NS, 256>>>(h, symbols, gamma, beta);
    main_kernel<<<B, 256>>>(values, gamma, beta, out);
}